// round 15
// baseline (speedup 1.0000x reference)
#include <cuda_runtime.h>
#include <cstdint>

// RWKV7 WKV — chunked UT-transform, L=16 (v8 = R14 k1 + 512-thread k2,
// R11 memory layouts verbatim, all-lanes-active warp mappings).

#define HH 32
#define NN 64
#define L  16
#define NCMAX 256

typedef unsigned long long u64;

__device__ float g_At [NCMAX*HH*L*NN];
__device__ float g_Rt [NCMAX*HH*L*NN];
__device__ float g_Bh [NCMAX*HH*L*NN];
__device__ float g_Kh [NCMAX*HH*L*NN];
__device__ float g_MV [NCMAX*HH*L*NN];
__device__ float g_RKV[NCMAX*HH*L*NN];
__device__ float g_Ti [NCMAX*HH*L*L];
__device__ float g_RB [NCMAX*HH*L*L];
__device__ float g_wL [NCMAX*HH*NN];

__device__ __forceinline__ u64 fma2(u64 a, u64 b, u64 c) {
    u64 d; asm("fma.rn.f32x2 %0, %1, %2, %3;" : "=l"(d) : "l"(a), "l"(b), "l"(c)); return d;
}
__device__ __forceinline__ u64 add2(u64 a, u64 b) {
    u64 d; asm("add.rn.f32x2 %0, %1, %2;" : "=l"(d) : "l"(a), "l"(b)); return d;
}
__device__ __forceinline__ u64 mul2(u64 a, u64 b) {
    u64 d; asm("mul.rn.f32x2 %0, %1, %2;" : "=l"(d) : "l"(a), "l"(b)); return d;
}
__device__ __forceinline__ u64 bcast2(float x) {
    u64 d; asm("mov.b64 %0, {%1, %1};" : "=l"(d) : "f"(x)); return d;
}
__device__ __forceinline__ float hsum2(u64 a) {
    float x, y; asm("mov.b64 {%0, %1}, %2;" : "=f"(x), "=f"(y) : "l"(a)); return x + y;
}
__device__ __forceinline__ void cp_async16(void* smem_dst, const void* gsrc) {
    unsigned saddr = (unsigned)__cvta_generic_to_shared(smem_dst);
    asm volatile("cp.async.ca.shared.global [%0], [%1], 16;\n"
                 :: "r"(saddr), "l"(gsrc) : "memory");
}

// ================= kernel 1: per-chunk precompute (parallel, 256 thr) ======
__global__ __launch_bounds__(256)
void wkv7_k1(const float* __restrict__ rP, const float* __restrict__ wP,
             const float* __restrict__ kP, const float* __restrict__ vP,
             const float* __restrict__ aP, const float* __restrict__ bP)
{
    const int c = blockIdx.x >> 5, h = blockIdx.x & 31, tid = threadIdx.x;

    __shared__ float sW[L][68], sA[L][68], sB[L][68], sK[L][68], sR[L][68], sV[L][68];
    __shared__ float sC[L][17], sM[L][17], sRBm[L][17], sRKm[L][17], sTi[L][17];

    #pragma unroll
    for (int r = 0; r < 4; ++r) {
        int idx = tid + r*256;
        int tau = idx >> 6, j = idx & 63;
        size_t g = ((size_t)(c*L + tau) * HH + h) * NN + j;
        sW[tau][j] = fmaxf(wP[g], 1e-9f);
        sA[tau][j] = aP[g]; sB[tau][j] = bP[g]; sK[tau][j] = kP[g];
        sR[tau][j] = rP[g]; sV[tau][j] = vP[g];
    }
    __syncthreads();

    if (tid < NN) {
        float wv[L];
        #pragma unroll
        for (int tau = 0; tau < L; ++tau) wv[tau] = sW[tau][tid];
        float run = 1.f;
        #pragma unroll
        for (int tau = 0; tau < L; ++tau) { run *= wv[tau]; sW[tau][tid] = run; }
    }
    __syncthreads();

    #pragma unroll
    for (int r = 0; r < 4; ++r) {
        int idx = tid + r*256;
        int tau = idx >> 6, j = idx & 63;
        float Wc = sW[tau][j];
        float Wp = tau ? sW[tau-1][j] : 1.f;
        float inv = 1.f / Wc;
        sA[tau][j] *= Wp; sB[tau][j] *= inv; sK[tau][j] *= inv; sR[tau][j] *= Wc;
    }
    __syncthreads();

    {
        const int s = tid & 15, tau = tid >> 4;
        const u64* Bp = (const u64*)&sB[s][0];
        const u64* Kp = (const u64*)&sK[s][0];
        const u64* Ap = (const u64*)&sA[tau][0];
        const u64* Rp = (const u64*)&sR[tau][0];
        u64 c1=0, m1=0, rb1=0, rk1=0;
        #pragma unroll 8
        for (int p = 0; p < 32; ++p) {
            u64 bs = Bp[p], ks = Kp[p], a1 = Ap[p], r1 = Rp[p];
            c1 = fma2(a1, bs, c1);   m1 = fma2(a1, ks, m1);
            rb1 = fma2(r1, bs, rb1); rk1 = fma2(r1, ks, rk1);
        }
        float fc=hsum2(c1), fm=hsum2(m1), frb=hsum2(rb1), frk=hsum2(rk1);
        if (s >  tau) { frb = 0.f; frk = 0.f; }
        if (s >= tau) { fc = 0.f;  fm = 0.f; }
        sC[tau][s]=fc; sM[tau][s]=fm; sRBm[tau][s]=frb; sRKm[tau][s]=frk;
    }
    __syncthreads();

    if (tid < L) {
        const int s = tid;
        float col[L];
        #pragma unroll
        for (int tau = 0; tau < L; ++tau) {
            float x = (tau == s) ? 1.f : 0.f;
            #pragma unroll
            for (int u = 0; u < L; ++u)
                if (u < tau) x = fmaf(sC[tau][u], col[u], x);
            col[tau] = x;
        }
        #pragma unroll
        for (int tau = 0; tau < L; ++tau) sTi[tau][s] = col[tau];
    }
    __syncthreads();

    const size_t LN = ((size_t)c*HH + h) * (L*NN);

    {
        const int tau = tid >> 4, i4 = (tid & 15) * 4;
        u64 mv0=0, mv1=0, rk0=0, rk1=0;
        #pragma unroll
        for (int s = 0; s < L; ++s) {
            const u64* vp = (const u64*)&sV[s][i4];
            u64 v0 = vp[0], v1 = vp[1];
            u64 m2b = bcast2(sM[tau][s]);
            u64 k2b = bcast2(sRKm[tau][s]);
            mv0 = fma2(m2b, v0, mv0); mv1 = fma2(m2b, v1, mv1);
            rk0 = fma2(k2b, v0, rk0); rk1 = fma2(k2b, v1, rk1);
        }
        u64* od = (u64*)(g_MV + LN + tau*NN + i4);
        od[0] = mv0; od[1] = mv1;
        u64* od2 = (u64*)(g_RKV + LN + tau*NN + i4);
        od2[0] = rk0; od2[1] = rk1;
    }

    #pragma unroll
    for (int r = 0; r < 4; ++r) {
        int idx = tid + r*256;
        int tau = idx >> 6, j = idx & 63;
        float wl = sW[L-1][j];
        g_At[LN+idx] = sA[tau][j];
        g_Rt[LN+idx] = sR[tau][j];
        g_Bh[LN+idx] = sB[tau][j] * wl;
        g_Kh[LN+idx] = sK[tau][j] * wl;
    }
    const size_t Tb = ((size_t)c*HH + h) * (L*L);
    {
        g_Ti[Tb+tid] = sTi[tid>>4][tid&15];
        g_RB[Tb+tid] = sRBm[tid>>4][tid&15];
    }
    if (tid < NN) g_wL[((size_t)c*HH + h)*NN + tid] = sW[L-1][tid];
}

// ================= kernel 2: serial over chunks (512 threads) ==============
struct Stage {
    float Aq[L][68], Rq[L][68], Bq[L][68], Kq[L][68];
    float Ti[L][20], RBm[L][20];
    float MV[L][16], RKV[L][16], V[L][16];
    float wL[64];
};
#define STAGE_F ((int)(sizeof(Stage)/4))

__device__ __forceinline__ void loadStage(Stage& st, int c, int h, int i0, int tid,
                                          const float* __restrict__ vP)
{
    const size_t LN = ((size_t)c*HH + h) * (L*NN);
    const size_t Tb = ((size_t)c*HH + h) * (L*L);
    if (tid < 256) {
        int row = tid >> 4, q = (tid & 15) * 4;
        cp_async16(&st.Aq[row][q], g_At + LN + row*NN + q);
        cp_async16(&st.Rq[row][q], g_Rt + LN + row*NN + q);
    } else {
        int t = tid - 256;
        int row = t >> 4, q = (t & 15) * 4;
        cp_async16(&st.Bq[row][q], g_Bh + LN + row*NN + q);
        cp_async16(&st.Kq[row][q], g_Kh + LN + row*NN + q);
    }
    if (tid < 64) {
        int row = tid >> 2, q = (tid & 3) * 4;
        cp_async16(&st.Ti[row][q], g_Ti + Tb + row*L + q);
    } else if (tid < 128) {
        int e = tid - 64, row = e >> 2, q = (e & 3) * 4;
        cp_async16(&st.RBm[row][q], g_RB + Tb + row*L + q);
    } else if (tid < 192) {
        int e = tid - 128, row = e >> 2, q = (e & 3) * 4;
        cp_async16(&st.MV[row][q], g_MV + LN + row*NN + i0 + q);
    } else if (tid < 256) {
        int e = tid - 192, row = e >> 2, q = (e & 3) * 4;
        cp_async16(&st.RKV[row][q], g_RKV + LN + row*NN + i0 + q);
    } else if (tid < 320) {
        int e = tid - 256, row = e >> 2, q = (e & 3) * 4;
        cp_async16(&st.V[row][q], vP + ((size_t)(c*L + row)*HH + h)*NN + i0 + q);
    } else if (tid < 336) {
        int e = tid - 320;
        cp_async16(&st.wL[e*4], g_wL + ((size_t)c*HH + h)*NN + e*4);
    }
}

__global__ __launch_bounds__(512, 1)
void wkv7_k2(const float* __restrict__ vP, const float* __restrict__ stateP,
             float* __restrict__ yOut, float* __restrict__ sOut, int NC)
{
    extern __shared__ float dyn[];
    Stage* st = (Stage*)dyn;
    float* sS = dyn + 3*STAGE_F;            // [16][68]
    float* sG = sS + 16*68;                 // [16][17]
    float* sU = sG + 16*17;                 // [16][17]
    float* sY = sU + 16*17;                 // [16][17]

    const int tid = threadIdx.x;
    const int h  = blockIdx.x >> 2, sl = blockIdx.x & 3;
    const int i0 = sl * 16;

    const int warp = tid >> 5, lane = tid & 31;
    const int iL = lane & 15, hf = lane >> 4;   // hf in {0,1}
    const int tau = warp;                       // 16 warps <-> 16 taus
    const int jb  = warp * 4;                   // S-update 4-wide j-slice

    // ---- state into SMEM ----
    #pragma unroll
    for (int r = 0; r < 2; ++r) {
        int idx = tid + r*512;
        int si = idx >> 6, j = idx & 63;
        sS[si*68 + j] = stateP[((size_t)h*NN + i0 + si)*NN + j];
    }

    if (NC > 0) loadStage(st[0], 0, h, i0, tid, vP);
    asm volatile("cp.async.commit_group;\n" ::: "memory");
    if (NC > 1) loadStage(st[1], 1, h, i0, tid, vP);
    asm volatile("cp.async.commit_group;\n" ::: "memory");

    #pragma unroll 1
    for (int c = 0; c < NC; ++c) {
        asm volatile("cp.async.wait_group 1;\n" ::: "memory");
        __syncthreads();
        if (c + 2 < NC) loadStage(st[(c+2)%3], c+2, h, i0, tid, vP);
        asm volatile("cp.async.commit_group;\n" ::: "memory");

        Stage& S = st[c % 3];

        // ---- stage 1: G[tau][iL] = A~[tau].S[iL], Y0 = R~[tau].S[iL] ----
        // thread covers j = hf*4 + p*8 (4 floats each), p=0..7 (32 j's)
        {
            const float* Ar  = &S.Aq[tau][hf*4];
            const float* Rr  = &S.Rq[tau][hf*4];
            const float* Srw = &sS[iL*68 + hf*4];
            u64 g0=0, g1=0, q0=0, q1=0;
            #pragma unroll
            for (int p = 0; p < 8; ++p) {
                ulonglong2 sv = *(const ulonglong2*)(Srw + p*8);
                ulonglong2 av = *(const ulonglong2*)(Ar + p*8);
                ulonglong2 rv = *(const ulonglong2*)(Rr + p*8);
                g0 = fma2(av.x, sv.x, g0); g1 = fma2(av.y, sv.y, g1);
                q0 = fma2(rv.x, sv.x, q0); q1 = fma2(rv.y, sv.y, q1);
            }
            float fg = hsum2(add2(g0, g1));
            float fy = hsum2(add2(q0, q1));
            fg += __shfl_xor_sync(0xffffffffu, fg, 16);
            fy += __shfl_xor_sync(0xffffffffu, fy, 16);
            if (hf == 0) {
                sG[tau*17 + iL] = fg + S.MV[tau][iL];
                sY[tau*17 + iL] = fy;
            }
        }
        __syncthreads();

        // ---- U[tau][iL] = Ti[tau,:].G[:,iL], s-range split over hf ----
        {
            float4 t0 = *(const float4*)&S.Ti[tau][hf*8];
            float4 t1 = *(const float4*)&S.Ti[tau][hf*8 + 4];
            const float* gcol = sG + iL + hf*8*17;
            float u;
            u = t0.x * gcol[0*17];
            u = fmaf(t0.y, gcol[1*17], u);
            u = fmaf(t0.z, gcol[2*17], u);
            u = fmaf(t0.w, gcol[3*17], u);
            u = fmaf(t1.x, gcol[4*17], u);
            u = fmaf(t1.y, gcol[5*17], u);
            u = fmaf(t1.z, gcol[6*17], u);
            u = fmaf(t1.w, gcol[7*17], u);
            u += __shfl_xor_sync(0xffffffffu, u, 16);
            if (hf == 0) sU[tau*17 + iL] = u;
        }
        __syncthreads();

        // ---- Y finalize: y = Y0 + RKV + RB[tau,:].U[:,iL] (split over hf) ----
        {
            float4 b0 = *(const float4*)&S.RBm[tau][hf*8];
            float4 b1 = *(const float4*)&S.RBm[tau][hf*8 + 4];
            const float* ucol = sU + iL + hf*8*17;
            float yv;
            yv = b0.x * ucol[0*17];
            yv = fmaf(b0.y, ucol[1*17], yv);
            yv = fmaf(b0.z, ucol[2*17], yv);
            yv = fmaf(b0.w, ucol[3*17], yv);
            yv = fmaf(b1.x, ucol[4*17], yv);
            yv = fmaf(b1.y, ucol[5*17], yv);
            yv = fmaf(b1.z, ucol[6*17], yv);
            yv = fmaf(b1.w, ucol[7*17], yv);
            yv += __shfl_xor_sync(0xffffffffu, yv, 16);
            if (hf == 0) {
                yv += sY[tau*17 + iL] + S.RKV[tau][iL];
                yOut[((size_t)(c*L + tau) * HH + h) * NN + i0 + iL] = yv;
            }
        }

        // ---- S update: warp j-slice [jb, jb+4); s-range split over hf ----
        {
            const float* ucol = sU + iL;
            u64* srow = (u64*)&sS[iL*68 + jb];
            u64 n0 = 0, n1 = 0;
            if (hf == 0) {
                const u64* wl = (const u64*)&S.wL[jb];
                n0 = mul2(srow[0], wl[0]);
                n1 = mul2(srow[1], wl[1]);
            }
            #pragma unroll
            for (int s8 = 0; s8 < 8; ++s8) {
                const int s = hf*8 + s8;
                u64 u2 = bcast2(ucol[s*17]);
                u64 v2 = bcast2(S.V[s][iL]);
                ulonglong2 bv = *(const ulonglong2*)&S.Bq[s][jb];
                ulonglong2 kv = *(const ulonglong2*)&S.Kq[s][jb];
                n0 = fma2(bv.x, u2, n0); n0 = fma2(kv.x, v2, n0);
                n1 = fma2(bv.y, u2, n1); n1 = fma2(kv.y, v2, n1);
            }
            u64 m0 = __shfl_xor_sync(0xffffffffu, n0, 16);
            u64 m1 = __shfl_xor_sync(0xffffffffu, n1, 16);
            n0 = add2(n0, m0);
            n1 = add2(n1, m1);
            if (hf == 0) { srow[0] = n0; srow[1] = n1; }
        }
    }

    // ---- final state ----
    __syncthreads();
    #pragma unroll
    for (int r = 0; r < 2; ++r) {
        int idx = tid + r*512;
        int si = idx >> 6, j = idx & 63;
        sOut[((size_t)h*NN + i0 + si)*NN + j] = sS[si*68 + j];
    }
}

extern "C" void kernel_launch(void* const* d_in, const int* in_sizes, int n_in,
                              void* d_out, int out_size)
{
    const float* r  = (const float*)d_in[0];
    const float* w  = (const float*)d_in[1];
    const float* k  = (const float*)d_in[2];
    const float* v  = (const float*)d_in[3];
    const float* a  = (const float*)d_in[4];
    const float* b  = (const float*)d_in[5];
    const float* st = (const float*)d_in[6];

    const int T  = in_sizes[0] / (HH * NN);
    const int NC = T / L;

    float* y    = (float*)d_out;
    float* sfin = y + (size_t)T * HH * NN;

    const int smem2 = (3*STAGE_F + 16*68 + 3*16*17) * 4;
    cudaFuncSetAttribute(wkv7_k2, cudaFuncAttributeMaxDynamicSharedMemorySize, smem2);

    wkv7_k1<<<NC * HH, 256>>>(r, w, k, v, a, b);
    wkv7_k2<<<HH * 4, 512, smem2>>>(v, st, y, sfin, NC);
}

// round 16
// speedup vs baseline: 1.1044x; 1.1044x over previous
#include <cuda_runtime.h>
#include <cstdint>

// RWKV7 WKV — chunked UT-transform, L=16 (v9).
// k1: per (chunk,head) precompute (parallel, 8192 CTAs, 256 thr) — R14.
// k2: serial over chunks, 256 CTAs (32 heads x 8 slices of 8 rows) x 256 thr,
//     2 CTAs/SM co-resident (independent barriers => real latency hiding),
//     R11-style wavefront-optimal warp mappings.

#define HH 32
#define NN 64
#define L  16
#define NCMAX 256
#define IR 8          // value rows per k2 CTA

typedef unsigned long long u64;

__device__ float g_At [NCMAX*HH*L*NN];
__device__ float g_Rt [NCMAX*HH*L*NN];
__device__ float g_Bh [NCMAX*HH*L*NN];
__device__ float g_Kh [NCMAX*HH*L*NN];
__device__ float g_MV [NCMAX*HH*L*NN];
__device__ float g_RKV[NCMAX*HH*L*NN];
__device__ float g_Ti [NCMAX*HH*L*L];
__device__ float g_RB [NCMAX*HH*L*L];
__device__ float g_wL [NCMAX*HH*NN];

__device__ __forceinline__ u64 fma2(u64 a, u64 b, u64 c) {
    u64 d; asm("fma.rn.f32x2 %0, %1, %2, %3;" : "=l"(d) : "l"(a), "l"(b), "l"(c)); return d;
}
__device__ __forceinline__ u64 add2(u64 a, u64 b) {
    u64 d; asm("add.rn.f32x2 %0, %1, %2;" : "=l"(d) : "l"(a), "l"(b)); return d;
}
__device__ __forceinline__ u64 mul2(u64 a, u64 b) {
    u64 d; asm("mul.rn.f32x2 %0, %1, %2;" : "=l"(d) : "l"(a), "l"(b)); return d;
}
__device__ __forceinline__ u64 bcast2(float x) {
    u64 d; asm("mov.b64 %0, {%1, %1};" : "=l"(d) : "f"(x)); return d;
}
__device__ __forceinline__ float hsum2(u64 a) {
    float x, y; asm("mov.b64 {%0, %1}, %2;" : "=f"(x), "=f"(y) : "l"(a)); return x + y;
}
__device__ __forceinline__ void cp_async16(void* smem_dst, const void* gsrc) {
    unsigned saddr = (unsigned)__cvta_generic_to_shared(smem_dst);
    asm volatile("cp.async.ca.shared.global [%0], [%1], 16;\n"
                 :: "r"(saddr), "l"(gsrc) : "memory");
}

// ================= kernel 1: per-chunk precompute (parallel, 256 thr) ======
__global__ __launch_bounds__(256)
void wkv7_k1(const float* __restrict__ rP, const float* __restrict__ wP,
             const float* __restrict__ kP, const float* __restrict__ vP,
             const float* __restrict__ aP, const float* __restrict__ bP)
{
    const int c = blockIdx.x >> 5, h = blockIdx.x & 31, tid = threadIdx.x;

    __shared__ float sW[L][68], sA[L][68], sB[L][68], sK[L][68], sR[L][68], sV[L][68];
    __shared__ float sC[L][17], sM[L][17], sRBm[L][17], sRKm[L][17], sTi[L][17];

    #pragma unroll
    for (int r = 0; r < 4; ++r) {
        int idx = tid + r*256;
        int tau = idx >> 6, j = idx & 63;
        size_t g = ((size_t)(c*L + tau) * HH + h) * NN + j;
        sW[tau][j] = fmaxf(wP[g], 1e-9f);
        sA[tau][j] = aP[g]; sB[tau][j] = bP[g]; sK[tau][j] = kP[g];
        sR[tau][j] = rP[g]; sV[tau][j] = vP[g];
    }
    __syncthreads();

    if (tid < NN) {
        float wv[L];
        #pragma unroll
        for (int tau = 0; tau < L; ++tau) wv[tau] = sW[tau][tid];
        float run = 1.f;
        #pragma unroll
        for (int tau = 0; tau < L; ++tau) { run *= wv[tau]; sW[tau][tid] = run; }
    }
    __syncthreads();

    #pragma unroll
    for (int r = 0; r < 4; ++r) {
        int idx = tid + r*256;
        int tau = idx >> 6, j = idx & 63;
        float Wc = sW[tau][j];
        float Wp = tau ? sW[tau-1][j] : 1.f;
        float inv = 1.f / Wc;
        sA[tau][j] *= Wp; sB[tau][j] *= inv; sK[tau][j] *= inv; sR[tau][j] *= Wc;
    }
    __syncthreads();

    {
        const int s = tid & 15, tau = tid >> 4;
        const u64* Bp = (const u64*)&sB[s][0];
        const u64* Kp = (const u64*)&sK[s][0];
        const u64* Ap = (const u64*)&sA[tau][0];
        const u64* Rp = (const u64*)&sR[tau][0];
        u64 c1=0, m1=0, rb1=0, rk1=0;
        #pragma unroll 8
        for (int p = 0; p < 32; ++p) {
            u64 bs = Bp[p], ks = Kp[p], a1 = Ap[p], r1 = Rp[p];
            c1 = fma2(a1, bs, c1);   m1 = fma2(a1, ks, m1);
            rb1 = fma2(r1, bs, rb1); rk1 = fma2(r1, ks, rk1);
        }
        float fc=hsum2(c1), fm=hsum2(m1), frb=hsum2(rb1), frk=hsum2(rk1);
        if (s >  tau) { frb = 0.f; frk = 0.f; }
        if (s >= tau) { fc = 0.f;  fm = 0.f; }
        sC[tau][s]=fc; sM[tau][s]=fm; sRBm[tau][s]=frb; sRKm[tau][s]=frk;
    }
    __syncthreads();

    if (tid < L) {
        const int s = tid;
        float col[L];
        #pragma unroll
        for (int tau = 0; tau < L; ++tau) {
            float x = (tau == s) ? 1.f : 0.f;
            #pragma unroll
            for (int u = 0; u < L; ++u)
                if (u < tau) x = fmaf(sC[tau][u], col[u], x);
            col[tau] = x;
        }
        #pragma unroll
        for (int tau = 0; tau < L; ++tau) sTi[tau][s] = col[tau];
    }
    __syncthreads();

    const size_t LN = ((size_t)c*HH + h) * (L*NN);

    {
        const int tau = tid >> 4, i4 = (tid & 15) * 4;
        u64 mv0=0, mv1=0, rk0=0, rk1=0;
        #pragma unroll
        for (int s = 0; s < L; ++s) {
            const u64* vp = (const u64*)&sV[s][i4];
            u64 v0 = vp[0], v1 = vp[1];
            u64 m2b = bcast2(sM[tau][s]);
            u64 k2b = bcast2(sRKm[tau][s]);
            mv0 = fma2(m2b, v0, mv0); mv1 = fma2(m2b, v1, mv1);
            rk0 = fma2(k2b, v0, rk0); rk1 = fma2(k2b, v1, rk1);
        }
        u64* od = (u64*)(g_MV + LN + tau*NN + i4);
        od[0] = mv0; od[1] = mv1;
        u64* od2 = (u64*)(g_RKV + LN + tau*NN + i4);
        od2[0] = rk0; od2[1] = rk1;
    }

    #pragma unroll
    for (int r = 0; r < 4; ++r) {
        int idx = tid + r*256;
        int tau = idx >> 6, j = idx & 63;
        float wl = sW[L-1][j];
        g_At[LN+idx] = sA[tau][j];
        g_Rt[LN+idx] = sR[tau][j];
        g_Bh[LN+idx] = sB[tau][j] * wl;
        g_Kh[LN+idx] = sK[tau][j] * wl;
    }
    const size_t Tb = ((size_t)c*HH + h) * (L*L);
    {
        g_Ti[Tb+tid] = sTi[tid>>4][tid&15];
        g_RB[Tb+tid] = sRBm[tid>>4][tid&15];
    }
    if (tid < NN) g_wL[((size_t)c*HH + h)*NN + tid] = sW[L-1][tid];
}

// ================= kernel 2: serial over chunks (256 CTAs x 256 thr) =======
struct Stage {
    float Aq[L][68], Rq[L][68], Bq[L][68], Kq[L][68];
    float Ti[L][20], RBm[L][20];
    float MV[L][IR], RKV[L][IR], V[L][IR];
    float wL[64];
};
#define STAGE_F ((int)(sizeof(Stage)/4))

__device__ __forceinline__ void loadStage(Stage& st, int c, int h, int i0, int tid,
                                          const float* __restrict__ vP)
{
    const size_t LN = ((size_t)c*HH + h) * (L*NN);
    const size_t Tb = ((size_t)c*HH + h) * (L*L);
    {
        int row = tid >> 4, q = (tid & 15) * 4;
        cp_async16(&st.Aq[row][q], g_At + LN + row*NN + q);
        cp_async16(&st.Rq[row][q], g_Rt + LN + row*NN + q);
        cp_async16(&st.Bq[row][q], g_Bh + LN + row*NN + q);
        cp_async16(&st.Kq[row][q], g_Kh + LN + row*NN + q);
    }
    if (tid < 128) {
        int sel = tid >> 6, e = tid & 63, row = e >> 2, q = (e & 3) * 4;
        if (sel == 0) cp_async16(&st.Ti [row][q], g_Ti + Tb + row*L + q);
        else          cp_async16(&st.RBm[row][q], g_RB + Tb + row*L + q);
    }
    if (tid < 96) {   // MV/RKV/V: 16 rows x 8 floats = 32 float4 each
        int sel = tid >> 5, e = tid & 31, row = e >> 1, q = (e & 1) * 4;
        if (sel == 0)      cp_async16(&st.MV [row][q], g_MV  + LN + row*NN + i0 + q);
        else if (sel == 1) cp_async16(&st.RKV[row][q], g_RKV + LN + row*NN + i0 + q);
        else               cp_async16(&st.V  [row][q],
                               vP + ((size_t)(c*L + row)*HH + h)*NN + i0 + q);
    }
    if (tid < 16) cp_async16(&st.wL[tid*4], g_wL + ((size_t)c*HH + h)*NN + tid*4);
}

__global__ __launch_bounds__(256, 2)
void wkv7_k2(const float* __restrict__ vP, const float* __restrict__ stateP,
             float* __restrict__ yOut, float* __restrict__ sOut, int NC)
{
    extern __shared__ float dyn[];
    Stage* st = (Stage*)dyn;
    float* sS = dyn + 3*STAGE_F;            // [8][68]
    float* sG = sS + IR*68;                 // [16][9]  (tau, ii)
    float* sU = sG + 16*9;                  // [16][9]
    float* sY = sU + 16*9;                  // [16][9]

    const int tid = threadIdx.x;
    const int h  = blockIdx.x >> 3, sl = blockIdx.x & 7;
    const int i0 = sl * IR;

    const int warp = tid >> 5, lane = tid & 31;
    // stage 1: warp owns taus {2w,2w+1}; lanes = (ii:8, jh:4), 16 j's/thread
    const int ii1 = lane & 7, jh = lane >> 3;
    const int tauA = warp*2, tauB = tauA + 1;
    // U / Yfin: tid<128: tau = tid>>3 (0..15), ii = tid&7
    const int tauU = tid >> 3, iiU = tid & 7;
    // S-update: warp owns j-slice [8w,8w+8); lanes = (ii:8, jq:4)
    const int jbase = warp*8 + (lane >> 3)*2;   // u64 start (2 floats)
    const int iiS = lane & 7;

    // ---- state rows into SMEM ----
    #pragma unroll
    for (int r = 0; r < 2; ++r) {
        int idx = tid + r*256;                 // 0..511
        int si = idx >> 6, j = idx & 63;
        sS[si*68 + j] = stateP[((size_t)h*NN + i0 + si)*NN + j];
    }

    if (NC > 0) loadStage(st[0], 0, h, i0, tid, vP);
    asm volatile("cp.async.commit_group;\n" ::: "memory");
    if (NC > 1) loadStage(st[1], 1, h, i0, tid, vP);
    asm volatile("cp.async.commit_group;\n" ::: "memory");

    #pragma unroll 1
    for (int c = 0; c < NC; ++c) {
        asm volatile("cp.async.wait_group 1;\n" ::: "memory");
        __syncthreads();
        if (c + 2 < NC) loadStage(st[(c+2)%3], c+2, h, i0, tid, vP);
        asm volatile("cp.async.commit_group;\n" ::: "memory");

        Stage& S = st[c % 3];

        // ---- stage 1: G[tau][ii] = A~[tau].S[ii], Y0 = R~[tau].S[ii] ----
        // thread covers 16 contiguous j's at jh*16
        {
            const float* Ar0 = &S.Aq[tauA][jh*16];
            const float* Ar1 = &S.Aq[tauB][jh*16];
            const float* Rr0 = &S.Rq[tauA][jh*16];
            const float* Rr1 = &S.Rq[tauB][jh*16];
            const float* Srw = &sS[ii1*68 + jh*16];
            u64 g0=0, g1=0, q0=0, q1=0;
            #pragma unroll
            for (int p = 0; p < 4; ++p) {
                ulonglong2 sv = *(const ulonglong2*)(Srw + p*4);
                ulonglong2 a0 = *(const ulonglong2*)(Ar0 + p*4);
                ulonglong2 a1 = *(const ulonglong2*)(Ar1 + p*4);
                ulonglong2 r0 = *(const ulonglong2*)(Rr0 + p*4);
                ulonglong2 r1 = *(const ulonglong2*)(Rr1 + p*4);
                g0 = fma2(a0.x, sv.x, g0); g0 = fma2(a0.y, sv.y, g0);
                g1 = fma2(a1.x, sv.x, g1); g1 = fma2(a1.y, sv.y, g1);
                q0 = fma2(r0.x, sv.x, q0); q0 = fma2(r0.y, sv.y, q0);
                q1 = fma2(r1.x, sv.x, q1); q1 = fma2(r1.y, sv.y, q1);
            }
            float fg0 = hsum2(g0), fg1 = hsum2(g1);
            float fy0 = hsum2(q0), fy1 = hsum2(q1);
            // reduce over jh (lane bits 3,4)
            fg0 += __shfl_xor_sync(0xffffffffu, fg0, 8);
            fg1 += __shfl_xor_sync(0xffffffffu, fg1, 8);
            fy0 += __shfl_xor_sync(0xffffffffu, fy0, 8);
            fy1 += __shfl_xor_sync(0xffffffffu, fy1, 8);
            fg0 += __shfl_xor_sync(0xffffffffu, fg0, 16);
            fg1 += __shfl_xor_sync(0xffffffffu, fg1, 16);
            fy0 += __shfl_xor_sync(0xffffffffu, fy0, 16);
            fy1 += __shfl_xor_sync(0xffffffffu, fy1, 16);
            if (jh == 0) {
                sG[tauA*9 + ii1] = fg0 + S.MV[tauA][ii1];
                sG[tauB*9 + ii1] = fg1 + S.MV[tauB][ii1];
                sY[tauA*9 + ii1] = fy0;
                sY[tauB*9 + ii1] = fy1;
            }
        }
        __syncthreads();

        // ---- U[tau][ii] = Ti[tau,:] . G[:,ii]  (tid < 128) ----
        if (tid < 128) {
            float4 t0 = *(const float4*)&S.Ti[tauU][0];
            float4 t1 = *(const float4*)&S.Ti[tauU][4];
            float4 t2 = *(const float4*)&S.Ti[tauU][8];
            float4 t3 = *(const float4*)&S.Ti[tauU][12];
            const float* gcol = sG + iiU;
            float u;
            u = t0.x * gcol[0*9];
            u = fmaf(t0.y, gcol[1*9], u);
            u = fmaf(t0.z, gcol[2*9], u);
            u = fmaf(t0.w, gcol[3*9], u);
            u = fmaf(t1.x, gcol[4*9], u);
            u = fmaf(t1.y, gcol[5*9], u);
            u = fmaf(t1.z, gcol[6*9], u);
            u = fmaf(t1.w, gcol[7*9], u);
            u = fmaf(t2.x, gcol[8*9], u);
            u = fmaf(t2.y, gcol[9*9], u);
            u = fmaf(t2.z, gcol[10*9], u);
            u = fmaf(t2.w, gcol[11*9], u);
            u = fmaf(t3.x, gcol[12*9], u);
            u = fmaf(t3.y, gcol[13*9], u);
            u = fmaf(t3.z, gcol[14*9], u);
            u = fmaf(t3.w, gcol[15*9], u);
            sU[tauU*9 + iiU] = u;
        }
        __syncthreads();

        // ---- Y finalize (tid < 128) ----
        if (tid < 128) {
            float yv = sY[tauU*9 + iiU] + S.RKV[tauU][iiU];
            float4 b0 = *(const float4*)&S.RBm[tauU][0];
            float4 b1 = *(const float4*)&S.RBm[tauU][4];
            float4 b2 = *(const float4*)&S.RBm[tauU][8];
            float4 b3 = *(const float4*)&S.RBm[tauU][12];
            const float* ucol = sU + iiU;
            yv = fmaf(b0.x, ucol[0*9], yv);
            yv = fmaf(b0.y, ucol[1*9], yv);
            yv = fmaf(b0.z, ucol[2*9], yv);
            yv = fmaf(b0.w, ucol[3*9], yv);
            yv = fmaf(b1.x, ucol[4*9], yv);
            yv = fmaf(b1.y, ucol[5*9], yv);
            yv = fmaf(b1.z, ucol[6*9], yv);
            yv = fmaf(b1.w, ucol[7*9], yv);
            yv = fmaf(b2.x, ucol[8*9], yv);
            yv = fmaf(b2.y, ucol[9*9], yv);
            yv = fmaf(b2.z, ucol[10*9], yv);
            yv = fmaf(b2.w, ucol[11*9], yv);
            yv = fmaf(b3.x, ucol[12*9], yv);
            yv = fmaf(b3.y, ucol[13*9], yv);
            yv = fmaf(b3.z, ucol[14*9], yv);
            yv = fmaf(b3.w, ucol[15*9], yv);
            yOut[((size_t)(c*L + tauU) * HH + h) * NN + i0 + iiU] = yv;
        }

        // ---- S update: warp's 8-wide j-slice; S = wL.S + B^T U + K^T V ----
        {
            u64* srow = (u64*)&sS[iiS*68 + jbase];
            const u64 wl = *(const u64*)&S.wL[jbase];
            const float* ucol = sU + iiS;
            u64 n = mul2(srow[0], wl);
            #pragma unroll
            for (int s = 0; s < L; ++s) {
                u64 u2 = bcast2(ucol[s*9]);
                u64 v2 = bcast2(S.V[s][iiS]);
                u64 bv = *(const u64*)&S.Bq[s][jbase];
                u64 kv = *(const u64*)&S.Kq[s][jbase];
                n = fma2(bv, u2, n);
                n = fma2(kv, v2, n);
            }
            srow[0] = n;
        }
    }

    // ---- final state ----
    __syncthreads();
    #pragma unroll
    for (int r = 0; r < 2; ++r) {
        int idx = tid + r*256;
        int si = idx >> 6, j = idx & 63;
        sOut[((size_t)h*NN + i0 + si)*NN + j] = sS[si*68 + j];
    }
}

extern "C" void kernel_launch(void* const* d_in, const int* in_sizes, int n_in,
                              void* d_out, int out_size)
{
    const float* r  = (const float*)d_in[0];
    const float* w  = (const float*)d_in[1];
    const float* k  = (const float*)d_in[2];
    const float* v  = (const float*)d_in[3];
    const float* a  = (const float*)d_in[4];
    const float* b  = (const float*)d_in[5];
    const float* st = (const float*)d_in[6];

    const int T  = in_sizes[0] / (HH * NN);
    const int NC = T / L;

    float* y    = (float*)d_out;
    float* sfin = y + (size_t)T * HH * NN;

    const int smem2 = (3*STAGE_F + IR*68 + 3*16*9) * 4;
    cudaFuncSetAttribute(wkv7_k2, cudaFuncAttributeMaxDynamicSharedMemorySize, smem2);

    wkv7_k1<<<NC * HH, 256>>>(r, w, k, v, a, b);
    wkv7_k2<<<HH * 8, 256, smem2>>>(v, st, y, sfin, NC);
}